// round 7
// baseline (speedup 1.0000x reference)
#include <cuda_runtime.h>

#define IMG    4096
#define TW     64
#define TH     128
#define KY     32
#define HALO   7
#define RW     (TW + 2*HALO)      // 78 raw columns
#define ROWS   (TH + 2*HALO)      // 142 smem rows
#define STRIDE 81                 // odd -> conflict-free column walks

__global__ __launch_bounds__(256, 3) void meanconv_ring_kernel(
    const float* __restrict__ x,
    const float* __restrict__ mask,
    float* __restrict__ out)
{
    __shared__ float R[ROWS * STRIDE];   // 142*81*4 = 44.9 KB

    const int t   = threadIdx.x;
    const int gx0 = blockIdx.x * TW;
    const int gy0 = blockIdx.y * TH;

    // ---- Load clamped raw tile (replicate padding == index clamp) ----
    for (int idx = t; idx < ROWS * RW; idx += 256) {
        int r = idx / RW;
        int c = idx - r * RW;
        int gy = gy0 - HALO + r; gy = min(max(gy, 0), IMG - 1);
        int gx = gx0 - HALO + c; gx = min(max(gx, 0), IMG - 1);
        R[r * STRIDE + 1 + c] = x[gy * IMG + gx];
    }
    __syncthreads();

    // ---- Horizontal prefix per row (142 threads, 78-step FADD chain) ----
    if (t < ROWS) {
        float* rp = &R[t * STRIDE];
        rp[0] = 0.0f;
        float acc = 0.0f;
        #pragma unroll 6
        for (int c = 1; c <= RW; c++) { acc += rp[c]; rp[c] = acc; }
    }
    __syncthreads();

    // ---- Sweep: 7 sliding vertical sums of horizontal window sums ----
    const int tx = t & (TW - 1);
    const int y0 = (t >> 6) * KY;          // 0,32,64,96

    // rs_p(r) = P[r][tx+8+p] - P[r][tx+7-p]
    const float* Rb = &R[tx + 8];
    #define RSROW(r, p) (Rb[(r) * STRIDE + (p)] - Rb[(r) * STRIDE - 1 - (p)])

    const float W1 = 1.0f/63.0f,  W2 = 1.0f/175.0f, W3 = 1.0f/343.0f,
                W4 = 1.0f/567.0f, W5 = 1.0f/847.0f, W6 = 1.0f/1183.0f,
                W7 = 1.0f/1575.0f;

    float g1[3], g2[5], g3[7], g4[9], g5[11], g6[13];     // 48 ring regs
    float B1, B2, B3, B4, B5, B6, B7;

    // ---- Init windows centered at output row y0 (smem row y0+7) ----
    // ring slot for init element i is exactly i (matches (J-1)%L schedule).
    B1 = 0.0f;
    #pragma unroll
    for (int i = 0; i < 3;  i++) { float v = RSROW(y0 + 6  + i, 1); g1[i] = v; B1 += v; }
    B2 = 0.0f;
    #pragma unroll
    for (int i = 0; i < 5;  i++) { float v = RSROW(y0 + 5  + i, 2); g2[i] = v; B2 += v; }
    B3 = 0.0f;
    #pragma unroll
    for (int i = 0; i < 7;  i++) { float v = RSROW(y0 + 4  + i, 3); g3[i] = v; B3 += v; }
    B4 = 0.0f;
    #pragma unroll
    for (int i = 0; i < 9;  i++) { float v = RSROW(y0 + 3  + i, 4); g4[i] = v; B4 += v; }
    B5 = 0.0f;
    #pragma unroll
    for (int i = 0; i < 11; i++) { float v = RSROW(y0 + 2  + i, 5); g5[i] = v; B5 += v; }
    B6 = 0.0f;
    #pragma unroll
    for (int i = 0; i < 13; i++) { float v = RSROW(y0 + 1  + i, 6); g6[i] = v; B6 += v; }
    B7 = 0.0f;
    #pragma unroll
    for (int i = 0; i < 15; i++) { float v = RSROW(y0 + 0  + i, 7); B7 += v; }

    const int g0 = (gy0 + y0) * IMG + gx0 + tx;

    {
        float acc =        W1 * B1;
        acc = fmaf(W2, B2, acc); acc = fmaf(W3, B3, acc);
        acc = fmaf(W4, B4, acc); acc = fmaf(W5, B5, acc);
        acc = fmaf(W6, B6, acc); acc = fmaf(W7, B7, acc);
        out[g0] = acc * mask[g0];
    }

    // ---- Steady state: macro-expanded, literal J => static ring slots ----
    #define STEP(J) { \
        float n1 = RSROW(y0 + (J) + 8,  1); \
        float n2 = RSROW(y0 + (J) + 9,  2); \
        float n3 = RSROW(y0 + (J) + 10, 3); \
        float n4 = RSROW(y0 + (J) + 11, 4); \
        float n5 = RSROW(y0 + (J) + 12, 5); \
        float n6 = RSROW(y0 + (J) + 13, 6); \
        float n7 = RSROW(y0 + (J) + 14, 7); \
        float o7 = RSROW(y0 + (J) - 1,  7); \
        B1 += n1 - g1[((J)-1) % 3];  g1[((J)-1) % 3]  = n1; \
        B2 += n2 - g2[((J)-1) % 5];  g2[((J)-1) % 5]  = n2; \
        B3 += n3 - g3[((J)-1) % 7];  g3[((J)-1) % 7]  = n3; \
        B4 += n4 - g4[((J)-1) % 9];  g4[((J)-1) % 9]  = n4; \
        B5 += n5 - g5[((J)-1) % 11]; g5[((J)-1) % 11] = n5; \
        B6 += n6 - g6[((J)-1) % 13]; g6[((J)-1) % 13] = n6; \
        B7 += n7 - o7; \
        float acc =        W1 * B1; \
        acc = fmaf(W2, B2, acc); acc = fmaf(W3, B3, acc); \
        acc = fmaf(W4, B4, acc); acc = fmaf(W5, B5, acc); \
        acc = fmaf(W6, B6, acc); acc = fmaf(W7, B7, acc); \
        const int gg = g0 + (J) * IMG; \
        out[gg] = acc * mask[gg]; }

    STEP(1);  STEP(2);  STEP(3);  STEP(4);  STEP(5);  STEP(6);  STEP(7);
    STEP(8);  STEP(9);  STEP(10); STEP(11); STEP(12); STEP(13); STEP(14);
    STEP(15); STEP(16); STEP(17); STEP(18); STEP(19); STEP(20); STEP(21);
    STEP(22); STEP(23); STEP(24); STEP(25); STEP(26); STEP(27); STEP(28);
    STEP(29); STEP(30); STEP(31);

    #undef STEP
    #undef RSROW
}

extern "C" void kernel_launch(void* const* d_in, const int* in_sizes, int n_in,
                              void* d_out, int out_size)
{
    (void)n_in; (void)in_sizes; (void)out_size;
    const float* x    = (const float*)d_in[0];
    const float* mask = (const float*)d_in[1];
    float* out        = (float*)d_out;

    dim3 grid(IMG / TW, IMG / TH);   // 64 x 32 tiles
    meanconv_ring_kernel<<<grid, 256>>>(x, mask, out);
}

// round 8
// speedup vs baseline: 1.0063x; 1.0063x over previous
#include <cuda_runtime.h>

#define IMG    4096
#define TW     64
#define TH     128
#define KY     32
#define HALO   7
#define RW     (TW + 2*HALO)      // 78 raw columns
#define ROWS   (TH + 2*HALO)      // 142 smem rows
#define STRIDE 81                 // odd -> conflict-free column walks

__global__ __launch_bounds__(256, 3) void meanconv_ringpf_kernel(
    const float* __restrict__ x,
    const float* __restrict__ mask,
    float* __restrict__ out)
{
    __shared__ float R[ROWS * STRIDE];   // 142*81*4 = 44.9 KB

    const int t   = threadIdx.x;
    const int gx0 = blockIdx.x * TW;
    const int gy0 = blockIdx.y * TH;

    // ---- Load clamped raw tile (replicate padding == index clamp) ----
    for (int idx = t; idx < ROWS * RW; idx += 256) {
        int r = idx / RW;
        int c = idx - r * RW;
        int gy = gy0 - HALO + r; gy = min(max(gy, 0), IMG - 1);
        int gx = gx0 - HALO + c; gx = min(max(gx, 0), IMG - 1);
        R[r * STRIDE + 1 + c] = x[gy * IMG + gx];
    }
    __syncthreads();

    // ---- Horizontal prefix per row (142 threads, 78-step FADD chain) ----
    if (t < ROWS) {
        float* rp = &R[t * STRIDE];
        rp[0] = 0.0f;
        float acc = 0.0f;
        #pragma unroll 6
        for (int c = 1; c <= RW; c++) { acc += rp[c]; rp[c] = acc; }
    }
    __syncthreads();

    // ---- Sweep: 7 sliding vertical sums of horizontal window sums ----
    const int tx = t & (TW - 1);
    const int y0 = (t >> 6) * KY;          // 0,32,64,96

    // rs_p(r) = P[r][tx+8+p] - P[r][tx+7-p]
    const float* Rb = &R[tx + 8];
    #define RSROW(r, p) (Rb[(r) * STRIDE + (p)] - Rb[(r) * STRIDE - 1 - (p)])

    const float W1 = 1.0f/63.0f,  W2 = 1.0f/175.0f, W3 = 1.0f/343.0f,
                W4 = 1.0f/567.0f, W5 = 1.0f/847.0f, W6 = 1.0f/1183.0f,
                W7 = 1.0f/1575.0f;

    float g1[3], g2[5], g3[7], g4[9], g5[11], g6[13];     // 48 ring regs
    float B1, B2, B3, B4, B5, B6, B7;

    const int g0 = (gy0 + y0) * IMG + gx0 + tx;

    // ---- Mask prefetch ring: masks for steps J..J+3 always in flight ----
    float m[4];
    m[0] = mask[g0];
    m[1] = mask[g0 + 1 * IMG];
    m[2] = mask[g0 + 2 * IMG];
    m[3] = mask[g0 + 3 * IMG];

    // ---- Init windows centered at output row y0 (smem row y0+7) ----
    B1 = 0.0f;
    #pragma unroll
    for (int i = 0; i < 3;  i++) { float v = RSROW(y0 + 6  + i, 1); g1[i] = v; B1 += v; }
    B2 = 0.0f;
    #pragma unroll
    for (int i = 0; i < 5;  i++) { float v = RSROW(y0 + 5  + i, 2); g2[i] = v; B2 += v; }
    B3 = 0.0f;
    #pragma unroll
    for (int i = 0; i < 7;  i++) { float v = RSROW(y0 + 4  + i, 3); g3[i] = v; B3 += v; }
    B4 = 0.0f;
    #pragma unroll
    for (int i = 0; i < 9;  i++) { float v = RSROW(y0 + 3  + i, 4); g4[i] = v; B4 += v; }
    B5 = 0.0f;
    #pragma unroll
    for (int i = 0; i < 11; i++) { float v = RSROW(y0 + 2  + i, 5); g5[i] = v; B5 += v; }
    B6 = 0.0f;
    #pragma unroll
    for (int i = 0; i < 13; i++) { float v = RSROW(y0 + 1  + i, 6); g6[i] = v; B6 += v; }
    B7 = 0.0f;
    #pragma unroll
    for (int i = 0; i < 15; i++) { float v = RSROW(y0 + 0  + i, 7); B7 += v; }

    {
        float acc =        W1 * B1;
        acc = fmaf(W2, B2, acc); acc = fmaf(W3, B3, acc);
        acc = fmaf(W4, B4, acc); acc = fmaf(W5, B5, acc);
        acc = fmaf(W6, B6, acc); acc = fmaf(W7, B7, acc);
        out[g0] = acc * m[0];
        m[0] = mask[g0 + 4 * IMG];         // refill slot 0 for step J=4
    }

    // ---- Steady state: literal J => static ring slots; mask 4 steps ahead ----
    #define STEP(J) { \
        float n1 = RSROW(y0 + (J) + 8,  1); \
        float n2 = RSROW(y0 + (J) + 9,  2); \
        float n3 = RSROW(y0 + (J) + 10, 3); \
        float n4 = RSROW(y0 + (J) + 11, 4); \
        float n5 = RSROW(y0 + (J) + 12, 5); \
        float n6 = RSROW(y0 + (J) + 13, 6); \
        float n7 = RSROW(y0 + (J) + 14, 7); \
        float o7 = RSROW(y0 + (J) - 1,  7); \
        B1 += n1 - g1[((J)-1) % 3];  g1[((J)-1) % 3]  = n1; \
        B2 += n2 - g2[((J)-1) % 5];  g2[((J)-1) % 5]  = n2; \
        B3 += n3 - g3[((J)-1) % 7];  g3[((J)-1) % 7]  = n3; \
        B4 += n4 - g4[((J)-1) % 9];  g4[((J)-1) % 9]  = n4; \
        B5 += n5 - g5[((J)-1) % 11]; g5[((J)-1) % 11] = n5; \
        B6 += n6 - g6[((J)-1) % 13]; g6[((J)-1) % 13] = n6; \
        B7 += n7 - o7; \
        float acc =        W1 * B1; \
        acc = fmaf(W2, B2, acc); acc = fmaf(W3, B3, acc); \
        acc = fmaf(W4, B4, acc); acc = fmaf(W5, B5, acc); \
        acc = fmaf(W6, B6, acc); acc = fmaf(W7, B7, acc); \
        out[g0 + (J) * IMG] = acc * m[(J) % 4]; \
        if ((J) + 4 < KY) m[(J) % 4] = mask[g0 + ((J) + 4) * IMG]; }

    STEP(1);  STEP(2);  STEP(3);  STEP(4);  STEP(5);  STEP(6);  STEP(7);
    STEP(8);  STEP(9);  STEP(10); STEP(11); STEP(12); STEP(13); STEP(14);
    STEP(15); STEP(16); STEP(17); STEP(18); STEP(19); STEP(20); STEP(21);
    STEP(22); STEP(23); STEP(24); STEP(25); STEP(26); STEP(27); STEP(28);
    STEP(29); STEP(30); STEP(31);

    #undef STEP
    #undef RSROW
}

extern "C" void kernel_launch(void* const* d_in, const int* in_sizes, int n_in,
                              void* d_out, int out_size)
{
    (void)n_in; (void)in_sizes; (void)out_size;
    const float* x    = (const float*)d_in[0];
    const float* mask = (const float*)d_in[1];
    float* out        = (float*)d_out;

    dim3 grid(IMG / TW, IMG / TH);   // 64 x 32 tiles
    meanconv_ringpf_kernel<<<grid, 256>>>(x, mask, out);
}

// round 9
// speedup vs baseline: 1.0889x; 1.0821x over previous
#include <cuda_runtime.h>

#define IMG    4096
#define TW     64
#define TH     64
#define KY     32
#define HALO   7
#define RW     (TW + 2*HALO)      // 78 raw columns
#define ROWS   (TH + 2*HALO)      // 78 smem rows
#define STRIDE 81                 // 81%32=17, gcd=1 -> conflict-free column walks

__global__ __launch_bounds__(128, 8) void meanconv_r9_kernel(
    const float* __restrict__ x,
    const float* __restrict__ mask,
    float* __restrict__ out)
{
    __shared__ float R[ROWS * STRIDE];   // 78*81*4 = 25.3 KB

    const int t   = threadIdx.x;          // 0..127
    const int gx0 = blockIdx.x * TW;
    const int gy0 = blockIdx.y * TH;

    // ---- Load clamped raw tile (replicate padding == index clamp) ----
    for (int idx = t; idx < ROWS * RW; idx += 128) {
        int r = idx / RW;
        int c = idx - r * RW;
        int gy = gy0 - HALO + r; gy = min(max(gy, 0), IMG - 1);
        int gx = gx0 - HALO + c; gx = min(max(gx, 0), IMG - 1);
        R[r * STRIDE + 1 + c] = x[gy * IMG + gx];
    }
    __syncthreads();

    // ---- Horizontal prefix, segmented halves (156 segments, 128 threads) ----
    for (int s = t; s < 2 * ROWS; s += 128) {
        const int half = (s >= ROWS);
        const int row  = half ? s - ROWS : s;
        float* rp = &R[row * STRIDE];
        if (!half) {
            rp[0] = 0.0f;
            float acc = 0.0f;
            #pragma unroll
            for (int c = 1; c <= 39; c++) { acc += rp[c]; rp[c] = acc; }
        } else {
            float acc = 0.0f;
            #pragma unroll
            for (int c = 40; c <= 78; c++) { acc += rp[c]; rp[c] = acc; }
        }
    }
    __syncthreads();

    // ---- Fix-up: add first-half total to second half (78 threads) ----
    if (t < ROWS) {
        float* rp = &R[t * STRIDE];
        const float tot = rp[39];
        #pragma unroll 8
        for (int c = 40; c <= 78; c++) rp[c] += tot;
    }
    __syncthreads();

    // ---- Sweep: rings p=1..4 (24 regs), smem re-read p=5..7 ----
    const int tx = t & (TW - 1);
    const int y0 = (t >> 6) * KY;          // 0 or 32

    // rs_p(r) = P[r][tx+8+p] - P[r][tx+7-p]
    const float* Rb = &R[tx + 8];
    #define RSROW(r, p) (Rb[(r) * STRIDE + (p)] - Rb[(r) * STRIDE - 1 - (p)])

    const float W1 = 1.0f/63.0f,  W2 = 1.0f/175.0f, W3 = 1.0f/343.0f,
                W4 = 1.0f/567.0f, W5 = 1.0f/847.0f, W6 = 1.0f/1183.0f,
                W7 = 1.0f/1575.0f;

    float g1[3], g2[5], g3[7], g4[9];     // 24 ring regs
    float B1, B2, B3, B4, B5, B6, B7;

    // ---- Init windows centered at output row y0 (smem row y0+7) ----
    B1 = 0.0f;
    #pragma unroll
    for (int i = 0; i < 3;  i++) { float v = RSROW(y0 + 6 + i, 1); g1[i] = v; B1 += v; }
    B2 = 0.0f;
    #pragma unroll
    for (int i = 0; i < 5;  i++) { float v = RSROW(y0 + 5 + i, 2); g2[i] = v; B2 += v; }
    B3 = 0.0f;
    #pragma unroll
    for (int i = 0; i < 7;  i++) { float v = RSROW(y0 + 4 + i, 3); g3[i] = v; B3 += v; }
    B4 = 0.0f;
    #pragma unroll
    for (int i = 0; i < 9;  i++) { float v = RSROW(y0 + 3 + i, 4); g4[i] = v; B4 += v; }
    B5 = 0.0f;
    #pragma unroll
    for (int i = 0; i < 11; i++) B5 += RSROW(y0 + 2 + i, 5);
    B6 = 0.0f;
    #pragma unroll
    for (int i = 0; i < 13; i++) B6 += RSROW(y0 + 1 + i, 6);
    B7 = 0.0f;
    #pragma unroll
    for (int i = 0; i < 15; i++) B7 += RSROW(y0 + 0 + i, 7);

    const int g0 = (gy0 + y0) * IMG + gx0 + tx;

    {
        float acc =        W1 * B1;
        acc = fmaf(W2, B2, acc); acc = fmaf(W3, B3, acc);
        acc = fmaf(W4, B4, acc); acc = fmaf(W5, B5, acc);
        acc = fmaf(W6, B6, acc); acc = fmaf(W7, B7, acc);
        out[g0] = acc * mask[g0];
    }

    // ---- Steady state: literal J => static ring slots & immediate offsets ----
    #define STEP(J) { \
        float n1 = RSROW(y0 + (J) + 8,  1); \
        float n2 = RSROW(y0 + (J) + 9,  2); \
        float n3 = RSROW(y0 + (J) + 10, 3); \
        float n4 = RSROW(y0 + (J) + 11, 4); \
        float n5 = RSROW(y0 + (J) + 12, 5); float o5 = RSROW(y0 + (J) + 1, 5); \
        float n6 = RSROW(y0 + (J) + 13, 6); float o6 = RSROW(y0 + (J),     6); \
        float n7 = RSROW(y0 + (J) + 14, 7); float o7 = RSROW(y0 + (J) - 1, 7); \
        B1 += n1 - g1[((J)-1) % 3];  g1[((J)-1) % 3]  = n1; \
        B2 += n2 - g2[((J)-1) % 5];  g2[((J)-1) % 5]  = n2; \
        B3 += n3 - g3[((J)-1) % 7];  g3[((J)-1) % 7]  = n3; \
        B4 += n4 - g4[((J)-1) % 9];  g4[((J)-1) % 9]  = n4; \
        B5 += n5 - o5; \
        B6 += n6 - o6; \
        B7 += n7 - o7; \
        float acc =        W1 * B1; \
        acc = fmaf(W2, B2, acc); acc = fmaf(W3, B3, acc); \
        acc = fmaf(W4, B4, acc); acc = fmaf(W5, B5, acc); \
        acc = fmaf(W6, B6, acc); acc = fmaf(W7, B7, acc); \
        const int gg = g0 + (J) * IMG; \
        out[gg] = acc * mask[gg]; }

    STEP(1);  STEP(2);  STEP(3);  STEP(4);  STEP(5);  STEP(6);  STEP(7);
    STEP(8);  STEP(9);  STEP(10); STEP(11); STEP(12); STEP(13); STEP(14);
    STEP(15); STEP(16); STEP(17); STEP(18); STEP(19); STEP(20); STEP(21);
    STEP(22); STEP(23); STEP(24); STEP(25); STEP(26); STEP(27); STEP(28);
    STEP(29); STEP(30); STEP(31);

    #undef STEP
    #undef RSROW
}

extern "C" void kernel_launch(void* const* d_in, const int* in_sizes, int n_in,
                              void* d_out, int out_size)
{
    (void)n_in; (void)in_sizes; (void)out_size;
    const float* x    = (const float*)d_in[0];
    const float* mask = (const float*)d_in[1];
    float* out        = (float*)d_out;

    dim3 grid(IMG / TW, IMG / TH);   // 64 x 64 tiles, 128-thread CTAs
    meanconv_r9_kernel<<<grid, 128>>>(x, mask, out);
}

// round 13
// speedup vs baseline: 1.3977x; 1.2836x over previous
#include <cuda_runtime.h>

#define IMG 4096
#define OT   64                 // output tile edge
#define HALO 7
#define IT   (OT + 2*HALO)      // 78 input tile edge
#define SR   (IT + 1)           // 79 SAT rows/cols (zero border at row/col 0)
#define STRIDE 85               // gcd(85,32)=1 -> conflict-free everywhere

__global__ __launch_bounds__(256, 4) void meanconv_satcse_kernel(
    const float* __restrict__ x,
    const float* __restrict__ mask,
    float* __restrict__ out)
{
    __shared__ float T[SR * STRIDE];   // 79*85*4 = 26.9 KB

    const int t   = threadIdx.x;
    const int gx0 = blockIdx.x * OT;
    const int gy0 = blockIdx.y * OT;

    // Zero SAT border (row 0 and col 0)
    for (int i = t; i < SR; i += 256) { T[i] = 0.0f; T[i * STRIDE] = 0.0f; }

    // Load 78x78 clamped input tile (clamping == replicate padding)
    for (int idx = t; idx < IT * IT; idx += 256) {
        int r = idx / IT;
        int c = idx - r * IT;
        int gy = gy0 - HALO + r; gy = min(max(gy, 0), IMG - 1);
        int gx = gx0 - HALO + c; gx = min(max(gx, 0), IMG - 1);
        T[(r + 1) * STRIDE + (c + 1)] = __ldg(&x[gy * IMG + gx]);
    }
    __syncthreads();

    // Column prefix sums (thread per column)
    if (t < IT) {
        const int c = t + 1;
        float acc = 0.0f;
        #pragma unroll 6
        for (int r = 1; r < SR; r++) {
            acc += T[r * STRIDE + c];
            T[r * STRIDE + c] = acc;
        }
    }
    __syncthreads();

    // Row prefix sums (thread per row; stride 85 -> conflict-free)
    if (t < IT) {
        float* Trow = &T[(t + 1) * STRIDE];
        float acc = 0.0f;
        #pragma unroll 6
        for (int c = 1; c < SR; c++) {
            acc += Trow[c];
            Trow[c] = acc;
        }
    }
    __syncthreads();

    // ---- Query: per-scale corner-column streaming with explicit reuse ----
    // For scale p, outputs j=0..15 read SAT rows y0+7-p+rl (rl=0..16+2p) at
    // two fixed columns; each distinct value is loaded ONCE into d[] and
    // consumed by up to two outputs (bottom of j, top of j+2p+1).
    const int tx = t & (OT - 1);
    const int y0 = (t >> 6) * 16;   // 0,16,32,48

    const float W[8] = { 0.0f,
        1.0f/63.0f, 1.0f/175.0f, 1.0f/343.0f, 1.0f/567.0f,
        1.0f/847.0f, 1.0f/1183.0f, 1.0f/1575.0f };

    float acc[16];
    #pragma unroll
    for (int j = 0; j < 16; j++) acc[j] = 0.0f;

    #pragma unroll
    for (int p = 1; p <= 7; p++) {
        const int NR = 17 + 2 * p;                 // distinct rows this scale
        const float* Tl = &T[(y0 + HALO - p) * STRIDE + tx + HALO - p];      // left  col
        const float* Tr = &T[(y0 + HALO - p) * STRIDE + tx + HALO + 1 + p];  // right col
        const float wp = W[p];

        float d[31];                               // compile-time indexed -> regs
        #pragma unroll
        for (int rl = 0; rl < NR; rl++)
            d[rl] = Tr[rl * STRIDE] - Tl[rl * STRIDE];

        #pragma unroll
        for (int j = 0; j < 16; j++)
            acc[j] = fmaf(wp, d[j + 2 * p + 1] - d[j], acc[j]);
    }

    // ---- Masked store (coalesced) ----
    #pragma unroll
    for (int j = 0; j < 16; j++) {
        const int g = (gy0 + y0 + j) * IMG + (gx0 + tx);
        out[g] = acc[j] * __ldg(&mask[g]);
    }
}

extern "C" void kernel_launch(void* const* d_in, const int* in_sizes, int n_in,
                              void* d_out, int out_size)
{
    (void)n_in; (void)in_sizes; (void)out_size;
    const float* x    = (const float*)d_in[0];
    const float* mask = (const float*)d_in[1];
    float* out        = (float*)d_out;

    dim3 grid(IMG / OT, IMG / OT);   // 64 x 64 tiles
    meanconv_satcse_kernel<<<grid, 256>>>(x, mask, out);
}